// round 12
// baseline (speedup 1.0000x reference)
#include <cuda_runtime.h>
#include <cuda_fp16.h>
#include <cstddef>
#include <cstdint>

// Problem constants (fixed shapes from reference)
#define T_    4096
#define DIN   512
#define RR    4096
#define DOUT  512
#define NINT  (RR + DIN)   // 4608
#define LEAK_ 0.9f

#define ROWS_MAX   28           // ceil(4096/148)
#define C_SH       3584         // half-cols of each row resident in SMEM
#define C_SH4      (C_SH / 4)   // 896 float4 s-chunks / uint2 w-chunks per row
#define SMEM_BYTES ((size_t)ROWS_MAX * C_SH * 2 + RR * 4)  // 200704+16384=217088

#define TPB        512          // block size for the recurrence

// ---------------------------------------------------------------------------
// Scratch (static __device__ arrays; runtime allocation is forbidden)
// ---------------------------------------------------------------------------
__device__ float  g_u[(size_t)T_ * RR];        // 64 MB
__device__ float  g_states[(size_t)T_ * RR];   // 64 MB
__device__ __half g_wres_h[(size_t)RR * RR];   // 32 MB: fp16 copy of Wres

// Full barrier (fallback paths)
__device__ unsigned g_count = 0;
__device__ volatile unsigned g_gen = 0;
// Split-phase barrier: per-half monotonic arrival counters + step flags
__device__ unsigned g_cntA = 0;
__device__ unsigned g_cntB = 0;
__device__ volatile unsigned g_phA = 0;   // highest step whose half-A states are ready
__device__ volatile unsigned g_phB = 0;

__device__ __forceinline__ float ldcg(const float* p) { return __ldcg(p); }
__device__ __forceinline__ float4 ldcg4f(const float4* p) {
    float4 v;
    asm volatile("ld.global.cg.v4.f32 {%0,%1,%2,%3}, [%4];"
                 : "=f"(v.x), "=f"(v.y), "=f"(v.z), "=f"(v.w) : "l"(p));
    return v;
}
__device__ __forceinline__ uint4 ldcg4u(const uint4* p) {
    uint4 v;
    asm volatile("ld.global.cg.v4.u32 {%0,%1,%2,%3}, [%4];"
                 : "=r"(v.x), "=r"(v.y), "=r"(v.z), "=r"(v.w) : "l"(p));
    return v;
}
__device__ __forceinline__ uint2 ldcg2u(const uint2* p) {
    uint2 v;
    asm volatile("ld.global.cg.v2.u32 {%0,%1}, [%2];"
                 : "=r"(v.x), "=r"(v.y) : "l"(p));
    return v;
}

// 4 halves (uint2) * float4 -> acc
__device__ __forceinline__ void fma4(uint2 w, float4 s, float& acc)
{
    float2 f0 = __half22float2(*reinterpret_cast<const __half2*>(&w.x));
    float2 f1 = __half22float2(*reinterpret_cast<const __half2*>(&w.y));
    acc = fmaf(f0.x, s.x, acc); acc = fmaf(f0.y, s.y, acc);
    acc = fmaf(f1.x, s.z, acc); acc = fmaf(f1.y, s.w, acc);
}
// 8 halves (uint4) * (float4,float4) -> acc
__device__ __forceinline__ void fma8(uint4 w, float4 s0, float4 s1, float& acc)
{
    float2 f;
    f = __half22float2(*reinterpret_cast<const __half2*>(&w.x));
    acc = fmaf(f.x, s0.x, acc); acc = fmaf(f.y, s0.y, acc);
    f = __half22float2(*reinterpret_cast<const __half2*>(&w.y));
    acc = fmaf(f.x, s0.z, acc); acc = fmaf(f.y, s0.w, acc);
    f = __half22float2(*reinterpret_cast<const __half2*>(&w.z));
    acc = fmaf(f.x, s1.x, acc); acc = fmaf(f.y, s1.y, acc);
    f = __half22float2(*reinterpret_cast<const __half2*>(&w.w));
    acc = fmaf(f.x, s1.z, acc); acc = fmaf(f.y, s1.w, acc);
}

// ---------------------------------------------------------------------------
// Full single-line barrier (fallback kernels)
// ---------------------------------------------------------------------------
__device__ __forceinline__ void grid_barrier(int nctas)
{
    __syncthreads();
    if (threadIdx.x == 0) {
        __threadfence();
        unsigned gen = g_gen;
        if (atomicAdd(&g_count, 1u) == (unsigned)(nctas - 1)) {
            g_count = 0;
            __threadfence();
            g_gen = gen + 1u;
        } else {
            while (g_gen == gen) { __nanosleep(64); }
        }
        __threadfence();
    }
    __syncthreads();
}

// Split-phase helpers (thread 0 only; __syncthreads around call sites)
__device__ __forceinline__ void half_arrive(int half, unsigned halfsize)
{
    __threadfence();                              // own stores -> L2
    unsigned old = (half == 0) ? atomicAdd(&g_cntA, 1u)
                               : atomicAdd(&g_cntB, 1u);
    if (((old + 1u) % halfsize) == 0u) {
        unsigned step = (old + 1u) / halfsize;
        __threadfence();
        if (half == 0) g_phA = step; else g_phB = step;
    }
}
__device__ __forceinline__ void half_wait(int half, unsigned want)
{
    if (half == 0) { while (g_phA < want) { __nanosleep(32); } }
    else           { while (g_phB < want) { __nanosleep(32); } }
    __threadfence();                              // acquire
}

__global__ void reset_barrier_kernel()
{
    if (threadIdx.x == 0) {
        g_count = 0; g_gen = 0;
        g_cntA = 0; g_cntB = 0; g_phA = 0; g_phB = 0;
    }
}

// ---------------------------------------------------------------------------
// Convert Wres fp32 -> fp16 (once per launch)
// ---------------------------------------------------------------------------
__global__ __launch_bounds__(256) void convert_wres_kernel(const float* __restrict__ W)
{
    const size_t n8 = (size_t)RR * RR / 8;
    uint4* out = reinterpret_cast<uint4*>(g_wres_h);
    const float4* in = reinterpret_cast<const float4*>(W);
    for (size_t k = (size_t)blockIdx.x * blockDim.x + threadIdx.x;
         k < n8; k += (size_t)gridDim.x * blockDim.x) {
        float4 a = ldcg4f(in + 2 * k);
        float4 b = ldcg4f(in + 2 * k + 1);
        uint4 o;
        __half2 h;
        h = __floats2half2_rn(a.x, a.y); o.x = *reinterpret_cast<uint32_t*>(&h);
        h = __floats2half2_rn(a.z, a.w); o.y = *reinterpret_cast<uint32_t*>(&h);
        h = __floats2half2_rn(b.x, b.y); o.z = *reinterpret_cast<uint32_t*>(&h);
        h = __floats2half2_rn(b.z, b.w); o.w = *reinterpret_cast<uint32_t*>(&h);
        out[k] = o;
    }
}

// ---------------------------------------------------------------------------
// GEMM 1: g_u[t][r] = sum_d x[t,d] * Win_w[r,d] + Win_b[r]
// ---------------------------------------------------------------------------
__global__ __launch_bounds__(256) void gemm_u_kernel(
    const float* __restrict__ A, const float* __restrict__ B,
    const float* __restrict__ bias)
{
    const int K = DIN;
    __shared__ float As[8][128];
    __shared__ float Bs[8][128];

    const int bm = blockIdx.y * 128;
    const int bn = blockIdx.x * 128;
    const int tid = threadIdx.x;
    const int tm = (tid >> 4) * 8;
    const int tn = (tid & 15) * 8;
    const int lr = tid >> 1;
    const int lc = (tid & 1) * 4;

    float acc[8][8];
    #pragma unroll
    for (int i = 0; i < 8; i++)
        #pragma unroll
        for (int j = 0; j < 8; j++) acc[i][j] = 0.f;

    for (int kb = 0; kb < K; kb += 8) {
        float4 a = *reinterpret_cast<const float4*>(&A[(size_t)(bm + lr) * K + kb + lc]);
        float4 b = *reinterpret_cast<const float4*>(&B[(size_t)(bn + lr) * K + kb + lc]);
        __syncthreads();
        As[lc + 0][lr] = a.x; As[lc + 1][lr] = a.y; As[lc + 2][lr] = a.z; As[lc + 3][lr] = a.w;
        Bs[lc + 0][lr] = b.x; Bs[lc + 1][lr] = b.y; Bs[lc + 2][lr] = b.z; Bs[lc + 3][lr] = b.w;
        __syncthreads();
        #pragma unroll
        for (int k = 0; k < 8; k++) {
            float4 a0 = *reinterpret_cast<const float4*>(&As[k][tm]);
            float4 a1 = *reinterpret_cast<const float4*>(&As[k][tm + 4]);
            float4 b0 = *reinterpret_cast<const float4*>(&Bs[k][tn]);
            float4 b1 = *reinterpret_cast<const float4*>(&Bs[k][tn + 4]);
            float ar[8] = {a0.x, a0.y, a0.z, a0.w, a1.x, a1.y, a1.z, a1.w};
            float br[8] = {b0.x, b0.y, b0.z, b0.w, b1.x, b1.y, b1.z, b1.w};
            #pragma unroll
            for (int i = 0; i < 8; i++)
                #pragma unroll
                for (int j = 0; j < 8; j++)
                    acc[i][j] = fmaf(ar[i], br[j], acc[i][j]);
        }
    }

    #pragma unroll
    for (int i = 0; i < 8; i++)
        #pragma unroll
        for (int j = 0; j < 8; j++)
            g_u[(size_t)(bm + tm + i) * RR + (bn + tn + j)] = acc[i][j] + bias[bn + tn + j];
}

// ---------------------------------------------------------------------------
// Split-phase persistent recurrence (requires nctas even).
// CTAs [0,n/2) own rows [0,rs) -> counter A; rest -> counter B.
// Per step: wait A -> stage+compute cols [0,rs); wait B -> stage+compute rest.
// 7 compute warps x 4 rows; SMEM weights cols [0,C_SH); register tail after.
// ---------------------------------------------------------------------------
extern __shared__ unsigned char s_dyn[];

__global__ __launch_bounds__(TPB, 1) void recur_split_kernel(int nctas)
{
    __half* wsh  = reinterpret_cast<__half*>(s_dyn);
    float*  s_sh = reinterpret_cast<float*>(s_dyn + (size_t)ROWS_MAX * C_SH * 2);
    float4* s_sh4 = reinterpret_cast<float4*>(s_sh);

    const int cta   = blockIdx.x;
    const int r0    = (cta * RR) / nctas;
    const int r1    = ((cta + 1) * RR) / nctas;
    const int nrows = r1 - r0;
    const int warp  = threadIdx.x >> 5;
    const int lane  = threadIdx.x & 31;
    const int tid   = threadIdx.x;

    const int nhalf  = nctas >> 1;
    const int myhalf = (cta < nhalf) ? 0 : 1;
    const unsigned hsz = (unsigned)nhalf;
    const int rs   = (nhalf * RR) / nctas;        // row/col split point (2048)
    const int C1_4 = rs / 4;                      // phase-1 float4 chunks (512)

    // Prologue: copy resident weight block (half) into SMEM
    {
        const int tot = nrows * (C_SH / 8);
        uint4* wsh4 = reinterpret_cast<uint4*>(wsh);
        for (int idx = tid; idx < tot; idx += TPB) {
            int lrow = idx / (C_SH / 8);
            int c8   = idx - lrow * (C_SH / 8);
            wsh4[(size_t)lrow * (C_SH / 8) + c8] =
                ldcg4u(reinterpret_cast<const uint4*>(g_wres_h + (size_t)(r0 + lrow) * RR) + c8);
        }
    }

    const int rowA   = r0 + 4 * warp;
    const bool active = (rowA < r1);
    bool rv[4];
    #pragma unroll
    for (int r = 0; r < 4; r++) rv[r] = active && (rowA + r < r1);

    // Register-resident tail weights (cols C_SH..RR-1), loaded ONCE.
    uint4 tw[4][2];
    #pragma unroll
    for (int r = 0; r < 4; r++)
        #pragma unroll
        for (int k = 0; k < 2; k++) {
            if (rv[r]) {
                const uint4* wg = reinterpret_cast<const uint4*>(
                    g_wres_h + (size_t)(rowA + r) * RR + C_SH);
                tw[r][k] = ldcg4u(wg + lane + 32 * k);
            } else {
                tw[r][k] = make_uint4(0, 0, 0, 0);
            }
        }

    const uint2* ws[4];
    #pragma unroll
    for (int r = 0; r < 4; r++)
        ws[r] = reinterpret_cast<const uint2*>(wsh + (size_t)(4 * warp + r) * C_SH);

    // step 0: states[0] = tanh(u[0])
    if (tid < nrows) {
        int r = r0 + tid;
        g_states[r] = tanhf(ldcg(&g_u[r]));
    }
    __syncthreads();
    if (tid == 0) half_arrive(myhalf, hsz);       // publishes step 1 when half done

    for (int t = 1; t < T_; ++t) {
        // Prefetch u[t] (independent of flags)
        float uval = 0.f;
        if (active && lane < 4 && rv[lane])
            uval = ldcg(&g_u[(size_t)t * RR + rowA + lane]);

        const float4* sp4 = reinterpret_cast<const float4*>(
            g_states + (size_t)(t - 1) * RR);

        // ---- phase 1: half-A states
        if (tid == 0) half_wait(0, (unsigned)t);
        __syncthreads();
        for (int i = tid; i < C1_4; i += TPB) s_sh4[i] = ldcg4f(sp4 + i);
        __syncthreads();

        float acc0 = 0.f, acc1 = 0.f, acc2 = 0.f, acc3 = 0.f;
        if (active) {
            #pragma unroll 4
            for (int idx = lane; idx < C1_4; idx += 32) {
                float4 s = s_sh4[idx];
                fma4(ws[0][idx], s, acc0);
                fma4(ws[1][idx], s, acc1);
                fma4(ws[2][idx], s, acc2);
                fma4(ws[3][idx], s, acc3);
            }
        }

        // ---- phase 2: half-B states
        if (tid == 0) half_wait(1, (unsigned)t);
        __syncthreads();
        for (int i = tid; i < RR / 4 - C1_4; i += TPB)
            s_sh4[C1_4 + i] = ldcg4f(sp4 + C1_4 + i);
        __syncthreads();

        if (active) {
            #pragma unroll 4
            for (int idx = C1_4 + lane; idx < C_SH4; idx += 32) {
                float4 s = s_sh4[idx];
                fma4(ws[0][idx], s, acc0);
                fma4(ws[1][idx], s, acc1);
                fma4(ws[2][idx], s, acc2);
                fma4(ws[3][idx], s, acc3);
            }
            #pragma unroll
            for (int k = 0; k < 2; k++) {
                int idx = lane + 32 * k;
                float4 s0 = s_sh4[C_SH / 4 + 2 * idx];
                float4 s1 = s_sh4[C_SH / 4 + 2 * idx + 1];
                fma8(tw[0][k], s0, s1, acc0);
                fma8(tw[1][k], s0, s1, acc1);
                fma8(tw[2][k], s0, s1, acc2);
                fma8(tw[3][k], s0, s1, acc3);
            }

            #pragma unroll
            for (int o = 16; o; o >>= 1) {
                acc0 += __shfl_xor_sync(0xffffffffu, acc0, o);
                acc1 += __shfl_xor_sync(0xffffffffu, acc1, o);
                acc2 += __shfl_xor_sync(0xffffffffu, acc2, o);
                acc3 += __shfl_xor_sync(0xffffffffu, acc3, o);
            }
            if (lane < 4 && rv[lane]) {
                float sum = (lane == 0) ? acc0 :
                            (lane == 1) ? acc1 :
                            (lane == 2) ? acc2 : acc3;
                int row = rowA + lane;
                float xi = tanhf(uval + sum);
                g_states[(size_t)t * RR + row] =
                    (1.0f - LEAK_) * s_sh[row] + LEAK_ * xi;
            }
        }
        __syncthreads();                          // block stores complete
        if (tid == 0) half_arrive(myhalf, hsz);   // publish step t+1
    }
}

// ---------------------------------------------------------------------------
// Non-split SMEM recurrence (R11; used when nctas is odd). Full barrier.
// ---------------------------------------------------------------------------
__global__ __launch_bounds__(TPB, 1) void recur_smem_kernel(int nctas)
{
    __half* wsh  = reinterpret_cast<__half*>(s_dyn);
    float*  s_sh = reinterpret_cast<float*>(s_dyn + (size_t)ROWS_MAX * C_SH * 2);
    float4* s_sh4 = reinterpret_cast<float4*>(s_sh);

    const int cta   = blockIdx.x;
    const int r0    = (cta * RR) / nctas;
    const int r1    = ((cta + 1) * RR) / nctas;
    const int nrows = r1 - r0;
    const int warp  = threadIdx.x >> 5;
    const int lane  = threadIdx.x & 31;
    const int tid   = threadIdx.x;

    {
        const int tot = nrows * (C_SH / 8);
        uint4* wsh4 = reinterpret_cast<uint4*>(wsh);
        for (int idx = tid; idx < tot; idx += TPB) {
            int lrow = idx / (C_SH / 8);
            int c8   = idx - lrow * (C_SH / 8);
            wsh4[(size_t)lrow * (C_SH / 8) + c8] =
                ldcg4u(reinterpret_cast<const uint4*>(g_wres_h + (size_t)(r0 + lrow) * RR) + c8);
        }
    }

    const int rowA   = r0 + 4 * warp;
    const bool active = (rowA < r1);
    bool rv[4];
    #pragma unroll
    for (int r = 0; r < 4; r++) rv[r] = active && (rowA + r < r1);

    uint4 tw[4][2];
    #pragma unroll
    for (int r = 0; r < 4; r++)
        #pragma unroll
        for (int k = 0; k < 2; k++) {
            if (rv[r]) {
                const uint4* wg = reinterpret_cast<const uint4*>(
                    g_wres_h + (size_t)(rowA + r) * RR + C_SH);
                tw[r][k] = ldcg4u(wg + lane + 32 * k);
            } else {
                tw[r][k] = make_uint4(0, 0, 0, 0);
            }
        }

    const uint2* ws[4];
    #pragma unroll
    for (int r = 0; r < 4; r++)
        ws[r] = reinterpret_cast<const uint2*>(wsh + (size_t)(4 * warp + r) * C_SH);

    if (tid < nrows) {
        int r = r0 + tid;
        g_states[r] = tanhf(ldcg(&g_u[r]));
    }
    grid_barrier(nctas);

    for (int t = 1; t < T_; ++t) {
        float uval = 0.f;
        if (active && lane < 4 && rv[lane])
            uval = ldcg(&g_u[(size_t)t * RR + rowA + lane]);

        {
            const float4* sp4 = reinterpret_cast<const float4*>(
                g_states + (size_t)(t - 1) * RR);
            s_sh4[tid]       = ldcg4f(sp4 + tid);
            s_sh4[tid + TPB] = ldcg4f(sp4 + tid + TPB);
        }
        __syncthreads();

        if (active) {
            float acc0 = 0.f, acc1 = 0.f, acc2 = 0.f, acc3 = 0.f;
            #pragma unroll 4
            for (int idx = lane; idx < C_SH4; idx += 32) {
                float4 s = s_sh4[idx];
                fma4(ws[0][idx], s, acc0);
                fma4(ws[1][idx], s, acc1);
                fma4(ws[2][idx], s, acc2);
                fma4(ws[3][idx], s, acc3);
            }
            #pragma unroll
            for (int k = 0; k < 2; k++) {
                int idx = lane + 32 * k;
                float4 s0 = s_sh4[C_SH / 4 + 2 * idx];
                float4 s1 = s_sh4[C_SH / 4 + 2 * idx + 1];
                fma8(tw[0][k], s0, s1, acc0);
                fma8(tw[1][k], s0, s1, acc1);
                fma8(tw[2][k], s0, s1, acc2);
                fma8(tw[3][k], s0, s1, acc3);
            }
            #pragma unroll
            for (int o = 16; o; o >>= 1) {
                acc0 += __shfl_xor_sync(0xffffffffu, acc0, o);
                acc1 += __shfl_xor_sync(0xffffffffu, acc1, o);
                acc2 += __shfl_xor_sync(0xffffffffu, acc2, o);
                acc3 += __shfl_xor_sync(0xffffffffu, acc3, o);
            }
            if (lane < 4 && rv[lane]) {
                float sum = (lane == 0) ? acc0 :
                            (lane == 1) ? acc1 :
                            (lane == 2) ? acc2 : acc3;
                int row = rowA + lane;
                float xi = tanhf(uval + sum);
                g_states[(size_t)t * RR + row] =
                    (1.0f - LEAK_) * s_sh[row] + LEAK_ * xi;
            }
        }
        grid_barrier(nctas);
    }
}

// ---------------------------------------------------------------------------
// Streaming fallback (no dynamic SMEM). Always resident.
// ---------------------------------------------------------------------------
__global__ __launch_bounds__(1024, 1) void recur_fallback(int nctas)
{
    __shared__ float fs[RR];
    float4* fs4 = reinterpret_cast<float4*>(fs);

    const int cta   = blockIdx.x;
    const int r0    = (cta * RR) / nctas;
    const int r1    = ((cta + 1) * RR) / nctas;
    const int nrows = r1 - r0;
    const int warp  = threadIdx.x >> 5;
    const int lane  = threadIdx.x & 31;
    const int tid   = threadIdx.x;

    if (tid < nrows) {
        int r = r0 + tid;
        g_states[r] = tanhf(ldcg(&g_u[r]));
    }
    grid_barrier(nctas);

    const int npairs = (nrows + 1) >> 1;
    const int rowA = r0 + 2 * warp;
    const int rowB = rowA + 1;
    const bool active = (warp < npairs);
    const bool haveB  = active && (rowB < r1);

    const uint2* wgA = reinterpret_cast<const uint2*>(g_wres_h + (size_t)rowA * RR);
    const uint2* wgB = reinterpret_cast<const uint2*>(g_wres_h + (size_t)rowB * RR);

    for (int t = 1; t < T_; ++t) {
        float uA = 0.f, uB = 0.f;
        if (active && lane == 0) {
            uA = ldcg(&g_u[(size_t)t * RR + rowA]);
            if (haveB) uB = ldcg(&g_u[(size_t)t * RR + rowB]);
        }
        {
            const float4* sp4 = reinterpret_cast<const float4*>(
                g_states + (size_t)(t - 1) * RR);
            fs4[tid] = ldcg4f(sp4 + tid);
        }
        __syncthreads();

        if (active) {
            float accA = 0.f, accB = 0.f;
            #pragma unroll 8
            for (int idx = lane; idx < RR / 4; idx += 32) {
                float4 s = fs4[idx];
                fma4(ldcg2u(wgA + idx), s, accA);
                if (haveB) fma4(ldcg2u(wgB + idx), s, accB);
            }
            #pragma unroll
            for (int o = 16; o; o >>= 1) {
                accA += __shfl_xor_sync(0xffffffffu, accA, o);
                accB += __shfl_xor_sync(0xffffffffu, accB, o);
            }
            if (lane == 0) {
                float* scur = g_states + (size_t)t * RR;
                float xiA = tanhf(uA + accA);
                scur[rowA] = (1.0f - LEAK_) * fs[rowA] + LEAK_ * xiA;
                if (haveB) {
                    float xiB = tanhf(uB + accB);
                    scur[rowB] = (1.0f - LEAK_) * fs[rowB] + LEAK_ * xiB;
                }
            }
        }
        grid_barrier(nctas);
    }
}

// ---------------------------------------------------------------------------
// GEMM 2: yout = concat(x, states) @ Wout^T + b
// ---------------------------------------------------------------------------
__global__ __launch_bounds__(256) void gemm_out_kernel(
    const float* __restrict__ x, const float* __restrict__ Wout,
    const float* __restrict__ bias, float* __restrict__ C)
{
    const int K = NINT;
    __shared__ float As[8][128];
    __shared__ float Bs[8][128];

    const int bm = blockIdx.y * 128;
    const int bn = blockIdx.x * 128;
    const int tid = threadIdx.x;
    const int tm = (tid >> 4) * 8;
    const int tn = (tid & 15) * 8;
    const int lr = tid >> 1;
    const int lc = (tid & 1) * 4;

    float acc[8][8];
    #pragma unroll
    for (int i = 0; i < 8; i++)
        #pragma unroll
        for (int j = 0; j < 8; j++) acc[i][j] = 0.f;

    for (int kb = 0; kb < K; kb += 8) {
        const int row = bm + lr;
        const int kk  = kb + lc;
        float4 a;
        if (kk < DIN)
            a = *reinterpret_cast<const float4*>(&x[(size_t)row * DIN + kk]);
        else
            a = *reinterpret_cast<const float4*>(&g_states[(size_t)row * RR + (kk - DIN)]);
        float4 b = *reinterpret_cast<const float4*>(&Wout[(size_t)(bn + lr) * K + kk]);
        __syncthreads();
        As[lc + 0][lr] = a.x; As[lc + 1][lr] = a.y; As[lc + 2][lr] = a.z; As[lc + 3][lr] = a.w;
        Bs[lc + 0][lr] = b.x; Bs[lc + 1][lr] = b.y; Bs[lc + 2][lr] = b.z; Bs[lc + 3][lr] = b.w;
        __syncthreads();
        #pragma unroll
        for (int k = 0; k < 8; k++) {
            float4 a0 = *reinterpret_cast<const float4*>(&As[k][tm]);
            float4 a1 = *reinterpret_cast<const float4*>(&As[k][tm + 4]);
            float4 b0 = *reinterpret_cast<const float4*>(&Bs[k][tn]);
            float4 b1 = *reinterpret_cast<const float4*>(&Bs[k][tn + 4]);
            float ar[8] = {a0.x, a0.y, a0.z, a0.w, a1.x, a1.y, a1.z, a1.w};
            float br[8] = {b0.x, b0.y, b0.z, b0.w, b1.x, b1.y, b1.z, b1.w};
            #pragma unroll
            for (int i = 0; i < 8; i++)
                #pragma unroll
                for (int j = 0; j < 8; j++)
                    acc[i][j] = fmaf(ar[i], br[j], acc[i][j]);
        }
    }

    #pragma unroll
    for (int i = 0; i < 8; i++)
        #pragma unroll
        for (int j = 0; j < 8; j++)
            C[(size_t)(bm + tm + i) * DOUT + (bn + tn + j)] = acc[i][j] + bias[bn + tn + j];
}

// ---------------------------------------------------------------------------
extern "C" void kernel_launch(void* const* d_in, const int* in_sizes, int n_in,
                              void* d_out, int out_size)
{
    const float* x      = (const float*)d_in[0];
    const float* Win_w  = (const float*)d_in[1];
    const float* Win_b  = (const float*)d_in[2];
    const float* Wres_w = (const float*)d_in[3];
    const float* Wout_w = (const float*)d_in[4];
    const float* Wout_b = (const float*)d_in[5];
    float* yout = (float*)d_out;

    int dev = 0;
    cudaGetDevice(&dev);
    int sms = 148;
    cudaDeviceGetAttribute(&sms, cudaDevAttrMultiProcessorCount, dev);
    if (sms < 64) sms = 64;
    if (sms > 256) sms = 256;

    cudaFuncSetAttribute(recur_split_kernel,
                         cudaFuncAttributeMaxDynamicSharedMemorySize, (int)SMEM_BYTES);
    cudaError_t attr_err = cudaFuncSetAttribute(
        recur_smem_kernel, cudaFuncAttributeMaxDynamicSharedMemorySize, (int)SMEM_BYTES);
    int nblk = 0;
    cudaError_t occ_err = cudaOccupancyMaxActiveBlocksPerMultiprocessor(
        &nblk, recur_smem_kernel, TPB, SMEM_BYTES);
    const int max_rows = (RR + sms - 1) / sms;
    const bool use_smem = (attr_err == cudaSuccess) &&
                          (occ_err == cudaSuccess) && (nblk >= 1) &&
                          (max_rows <= ROWS_MAX);

    reset_barrier_kernel<<<1, 32>>>();
    convert_wres_kernel<<<1024, 256>>>(Wres_w);

    dim3 g1(RR / 128, T_ / 128);
    gemm_u_kernel<<<g1, 256>>>(x, Win_w, Win_b);

    if (use_smem && (sms % 2 == 0))
        recur_split_kernel<<<sms, TPB, SMEM_BYTES>>>(sms);
    else if (use_smem)
        recur_smem_kernel<<<sms, TPB, SMEM_BYTES>>>(sms);
    else
        recur_fallback<<<sms, 1024>>>(sms);

    dim3 g2(DOUT / 128, T_ / 128);
    gemm_out_kernel<<<g2, 256>>>(x, Wout_w, Wout_b, yout);

    (void)in_sizes; (void)n_in; (void)out_size;
}

// round 13
// speedup vs baseline: 1.4452x; 1.4452x over previous
#include <cuda_runtime.h>
#include <cuda_fp16.h>
#include <cstddef>
#include <cstdint>

// Problem constants (fixed shapes from reference)
#define T_    4096
#define DIN   512
#define RR    4096
#define DOUT  512
#define NINT  (RR + DIN)   // 4608
#define LEAK_ 0.9f

#define ROWS_MAX   28           // ceil(4096/148)
#define C_SH       3584         // half-cols of each row resident in SMEM
#define C_SH4      (C_SH / 4)   // 896 float4 s-chunks / uint2 w-chunks per row
#define SMEM_BYTES ((size_t)ROWS_MAX * C_SH * 2 + RR * 4)  // 200704+16384=217088

#define TPB        512          // block size for the recurrence

// ---------------------------------------------------------------------------
// Scratch (static __device__ arrays; runtime allocation is forbidden)
// ---------------------------------------------------------------------------
__device__ float  g_u[(size_t)T_ * RR];        // 64 MB
__device__ float  g_states[(size_t)T_ * RR];   // 64 MB
__device__ __half g_wres_h[(size_t)RR * RR];   // 32 MB: fp16 copy of Wres

// Monotonic step barrier: g_count counts arrivals (never reset mid-run),
// g_gen publishes the last fully-arrived step.
__device__ unsigned g_count = 0;
__device__ unsigned g_gen = 0;

__device__ __forceinline__ float ldcg(const float* p) { return __ldcg(p); }
__device__ __forceinline__ float4 ldcg4f(const float4* p) {
    float4 v;
    asm volatile("ld.global.cg.v4.f32 {%0,%1,%2,%3}, [%4];"
                 : "=f"(v.x), "=f"(v.y), "=f"(v.z), "=f"(v.w) : "l"(p));
    return v;
}
__device__ __forceinline__ uint4 ldcg4u(const uint4* p) {
    uint4 v;
    asm volatile("ld.global.cg.v4.u32 {%0,%1,%2,%3}, [%4];"
                 : "=r"(v.x), "=r"(v.y), "=r"(v.z), "=r"(v.w) : "l"(p));
    return v;
}
__device__ __forceinline__ uint2 ldcg2u(const uint2* p) {
    uint2 v;
    asm volatile("ld.global.cg.v2.u32 {%0,%1}, [%2];"
                 : "=r"(v.x), "=r"(v.y) : "l"(p));
    return v;
}

// 4 halves (uint2) * float4 -> acc
__device__ __forceinline__ void fma4(uint2 w, float4 s, float& acc)
{
    float2 f0 = __half22float2(*reinterpret_cast<const __half2*>(&w.x));
    float2 f1 = __half22float2(*reinterpret_cast<const __half2*>(&w.y));
    acc = fmaf(f0.x, s.x, acc); acc = fmaf(f0.y, s.y, acc);
    acc = fmaf(f1.x, s.z, acc); acc = fmaf(f1.y, s.w, acc);
}
// 8 halves (uint4) * (float4,float4) -> acc
__device__ __forceinline__ void fma8(uint4 w, float4 s0, float4 s1, float& acc)
{
    float2 f;
    f = __half22float2(*reinterpret_cast<const __half2*>(&w.x));
    acc = fmaf(f.x, s0.x, acc); acc = fmaf(f.y, s0.y, acc);
    f = __half22float2(*reinterpret_cast<const __half2*>(&w.y));
    acc = fmaf(f.x, s0.z, acc); acc = fmaf(f.y, s0.w, acc);
    f = __half22float2(*reinterpret_cast<const __half2*>(&w.z));
    acc = fmaf(f.x, s1.x, acc); acc = fmaf(f.y, s1.y, acc);
    f = __half22float2(*reinterpret_cast<const __half2*>(&w.w));
    acc = fmaf(f.x, s1.z, acc); acc = fmaf(f.y, s1.w, acc);
}

// ---------------------------------------------------------------------------
// Monotonic scoped-atomic grid barrier.
// Arrival: atom.add.release.gpu (orders this CTA's prior stores; no fence).
// Last arrival of step publishes g_gen = step with st.release.
// Everyone (incl. releaser) leaves via an acquire-load of g_gen, which orders
// the subsequent .cg data loads. No CCTL.IVALL, no counter resets.
// 'step' is 1-based and strictly increasing across calls.
// ---------------------------------------------------------------------------
__device__ __forceinline__ void grid_barrier_step(int nctas, unsigned step)
{
    __syncthreads();
    if (threadIdx.x == 0) {
        unsigned old;
        asm volatile("atom.add.release.gpu.u32 %0, [%1], 1;"
                     : "=r"(old) : "l"(&g_count) : "memory");
        if (old + 1u == step * (unsigned)nctas) {
            asm volatile("st.release.gpu.u32 [%0], %1;"
                         :: "l"(&g_gen), "r"(step) : "memory");
        }
        unsigned cur;
        while (true) {
            asm volatile("ld.acquire.gpu.u32 %0, [%1];"
                         : "=r"(cur) : "l"(&g_gen) : "memory");
            if (cur >= step) break;
            __nanosleep(32);
        }
    }
    __syncthreads();
}

// ---------------------------------------------------------------------------
// Reset barrier state each launch (graph-replay invariant).
// ---------------------------------------------------------------------------
__global__ void reset_barrier_kernel()
{
    if (threadIdx.x == 0) { g_count = 0; g_gen = 0; }
}

// ---------------------------------------------------------------------------
// Convert Wres fp32 -> fp16 (once per launch)
// ---------------------------------------------------------------------------
__global__ __launch_bounds__(256) void convert_wres_kernel(const float* __restrict__ W)
{
    const size_t n8 = (size_t)RR * RR / 8;
    uint4* out = reinterpret_cast<uint4*>(g_wres_h);
    const float4* in = reinterpret_cast<const float4*>(W);
    for (size_t k = (size_t)blockIdx.x * blockDim.x + threadIdx.x;
         k < n8; k += (size_t)gridDim.x * blockDim.x) {
        float4 a = ldcg4f(in + 2 * k);
        float4 b = ldcg4f(in + 2 * k + 1);
        uint4 o;
        __half2 h;
        h = __floats2half2_rn(a.x, a.y); o.x = *reinterpret_cast<uint32_t*>(&h);
        h = __floats2half2_rn(a.z, a.w); o.y = *reinterpret_cast<uint32_t*>(&h);
        h = __floats2half2_rn(b.x, b.y); o.z = *reinterpret_cast<uint32_t*>(&h);
        h = __floats2half2_rn(b.z, b.w); o.w = *reinterpret_cast<uint32_t*>(&h);
        out[k] = o;
    }
}

// ---------------------------------------------------------------------------
// GEMM 1: g_u[t][r] = sum_d x[t,d] * Win_w[r,d] + Win_b[r]
// ---------------------------------------------------------------------------
__global__ __launch_bounds__(256) void gemm_u_kernel(
    const float* __restrict__ A, const float* __restrict__ B,
    const float* __restrict__ bias)
{
    const int K = DIN;
    __shared__ float As[8][128];
    __shared__ float Bs[8][128];

    const int bm = blockIdx.y * 128;
    const int bn = blockIdx.x * 128;
    const int tid = threadIdx.x;
    const int tm = (tid >> 4) * 8;
    const int tn = (tid & 15) * 8;
    const int lr = tid >> 1;
    const int lc = (tid & 1) * 4;

    float acc[8][8];
    #pragma unroll
    for (int i = 0; i < 8; i++)
        #pragma unroll
        for (int j = 0; j < 8; j++) acc[i][j] = 0.f;

    for (int kb = 0; kb < K; kb += 8) {
        float4 a = *reinterpret_cast<const float4*>(&A[(size_t)(bm + lr) * K + kb + lc]);
        float4 b = *reinterpret_cast<const float4*>(&B[(size_t)(bn + lr) * K + kb + lc]);
        __syncthreads();
        As[lc + 0][lr] = a.x; As[lc + 1][lr] = a.y; As[lc + 2][lr] = a.z; As[lc + 3][lr] = a.w;
        Bs[lc + 0][lr] = b.x; Bs[lc + 1][lr] = b.y; Bs[lc + 2][lr] = b.z; Bs[lc + 3][lr] = b.w;
        __syncthreads();
        #pragma unroll
        for (int k = 0; k < 8; k++) {
            float4 a0 = *reinterpret_cast<const float4*>(&As[k][tm]);
            float4 a1 = *reinterpret_cast<const float4*>(&As[k][tm + 4]);
            float4 b0 = *reinterpret_cast<const float4*>(&Bs[k][tn]);
            float4 b1 = *reinterpret_cast<const float4*>(&Bs[k][tn + 4]);
            float ar[8] = {a0.x, a0.y, a0.z, a0.w, a1.x, a1.y, a1.z, a1.w};
            float br[8] = {b0.x, b0.y, b0.z, b0.w, b1.x, b1.y, b1.z, b1.w};
            #pragma unroll
            for (int i = 0; i < 8; i++)
                #pragma unroll
                for (int j = 0; j < 8; j++)
                    acc[i][j] = fmaf(ar[i], br[j], acc[i][j]);
        }
    }

    #pragma unroll
    for (int i = 0; i < 8; i++)
        #pragma unroll
        for (int j = 0; j < 8; j++)
            g_u[(size_t)(bm + tm + i) * RR + (bn + tn + j)] = acc[i][j] + bias[bn + tn + j];
}

// ---------------------------------------------------------------------------
// Persistent recurrence (R11 structure), fp16 weights.
// Block 512. 7 compute warps x 4 rows. Cols [0,C_SH) in SMEM,
// cols [C_SH,RR) register-resident. s fp32 staged to SMEM per step.
// ---------------------------------------------------------------------------
extern __shared__ unsigned char s_dyn[];

__global__ __launch_bounds__(TPB, 1) void recur_smem_kernel(int nctas)
{
    __half* wsh  = reinterpret_cast<__half*>(s_dyn);
    float*  s_sh = reinterpret_cast<float*>(s_dyn + (size_t)ROWS_MAX * C_SH * 2);
    float4* s_sh4 = reinterpret_cast<float4*>(s_sh);

    const int cta   = blockIdx.x;
    const int r0    = (cta * RR) / nctas;
    const int r1    = ((cta + 1) * RR) / nctas;
    const int nrows = r1 - r0;
    const int warp  = threadIdx.x >> 5;
    const int lane  = threadIdx.x & 31;
    const int tid   = threadIdx.x;

    // Prologue: copy resident weight block (half) into SMEM (uint4 chunks)
    {
        const int tot = nrows * (C_SH / 8);
        uint4* wsh4 = reinterpret_cast<uint4*>(wsh);
        for (int idx = tid; idx < tot; idx += TPB) {
            int lrow = idx / (C_SH / 8);
            int c8   = idx - lrow * (C_SH / 8);
            wsh4[(size_t)lrow * (C_SH / 8) + c8] =
                ldcg4u(reinterpret_cast<const uint4*>(g_wres_h + (size_t)(r0 + lrow) * RR) + c8);
        }
    }

    const int rowA   = r0 + 4 * warp;
    const bool active = (rowA < r1);
    bool rv[4];
    #pragma unroll
    for (int r = 0; r < 4; r++) rv[r] = active && (rowA + r < r1);

    // Register-resident tail weights (cols C_SH..RR-1), loaded ONCE.
    uint4 tw[4][2];
    #pragma unroll
    for (int r = 0; r < 4; r++)
        #pragma unroll
        for (int k = 0; k < 2; k++) {
            if (rv[r]) {
                const uint4* wg = reinterpret_cast<const uint4*>(
                    g_wres_h + (size_t)(rowA + r) * RR + C_SH);
                tw[r][k] = ldcg4u(wg + lane + 32 * k);
            } else {
                tw[r][k] = make_uint4(0, 0, 0, 0);
            }
        }

    const uint2* ws[4];
    #pragma unroll
    for (int r = 0; r < 4; r++)
        ws[r] = reinterpret_cast<const uint2*>(wsh + (size_t)(4 * warp + r) * C_SH);

    // step 0: states[0] = tanh(u[0])
    if (tid < nrows) {
        int r = r0 + tid;
        g_states[r] = tanhf(ldcg(&g_u[r]));
    }
    unsigned bstep = 1;
    grid_barrier_step(nctas, bstep++);

    for (int t = 1; t < T_; ++t) {
        // Prefetch u[t] (independent of the barrier)
        float uval = 0.f;
        if (active && lane < 4 && rv[lane])
            uval = ldcg(&g_u[(size_t)t * RR + rowA + lane]);

        // Stage s_{t-1} into SMEM (published by the previous barrier)
        {
            const float4* sp4 = reinterpret_cast<const float4*>(
                g_states + (size_t)(t - 1) * RR);
            s_sh4[tid]       = ldcg4f(sp4 + tid);
            s_sh4[tid + TPB] = ldcg4f(sp4 + tid + TPB);
        }
        __syncthreads();

        if (active) {
            float acc0 = 0.f, acc1 = 0.f, acc2 = 0.f, acc3 = 0.f;

            #pragma unroll 4
            for (int idx = lane; idx < C_SH4; idx += 32) {
                float4 s = s_sh4[idx];
                fma4(ws[0][idx], s, acc0);
                fma4(ws[1][idx], s, acc1);
                fma4(ws[2][idx], s, acc2);
                fma4(ws[3][idx], s, acc3);
            }
            #pragma unroll
            for (int k = 0; k < 2; k++) {
                int idx = lane + 32 * k;
                float4 s0 = s_sh4[C_SH / 4 + 2 * idx];
                float4 s1 = s_sh4[C_SH / 4 + 2 * idx + 1];
                fma8(tw[0][k], s0, s1, acc0);
                fma8(tw[1][k], s0, s1, acc1);
                fma8(tw[2][k], s0, s1, acc2);
                fma8(tw[3][k], s0, s1, acc3);
            }

            #pragma unroll
            for (int o = 16; o; o >>= 1) {
                acc0 += __shfl_xor_sync(0xffffffffu, acc0, o);
                acc1 += __shfl_xor_sync(0xffffffffu, acc1, o);
                acc2 += __shfl_xor_sync(0xffffffffu, acc2, o);
                acc3 += __shfl_xor_sync(0xffffffffu, acc3, o);
            }
            if (lane < 4 && rv[lane]) {
                float sum = (lane == 0) ? acc0 :
                            (lane == 1) ? acc1 :
                            (lane == 2) ? acc2 : acc3;
                int row = rowA + lane;
                float xi = tanhf(uval + sum);
                g_states[(size_t)t * RR + row] =
                    (1.0f - LEAK_) * s_sh[row] + LEAK_ * xi;
            }
        }
        grid_barrier_step(nctas, bstep++);
    }
}

// ---------------------------------------------------------------------------
// Streaming fallback (no dynamic SMEM). Always resident.
// ---------------------------------------------------------------------------
__global__ __launch_bounds__(1024, 1) void recur_fallback(int nctas)
{
    __shared__ float fs[RR];
    float4* fs4 = reinterpret_cast<float4*>(fs);

    const int cta   = blockIdx.x;
    const int r0    = (cta * RR) / nctas;
    const int r1    = ((cta + 1) * RR) / nctas;
    const int nrows = r1 - r0;
    const int warp  = threadIdx.x >> 5;
    const int lane  = threadIdx.x & 31;
    const int tid   = threadIdx.x;

    if (tid < nrows) {
        int r = r0 + tid;
        g_states[r] = tanhf(ldcg(&g_u[r]));
    }
    unsigned bstep = 1;
    grid_barrier_step(nctas, bstep++);

    const int npairs = (nrows + 1) >> 1;
    const int rowA = r0 + 2 * warp;
    const int rowB = rowA + 1;
    const bool active = (warp < npairs);
    const bool haveB  = active && (rowB < r1);

    const uint2* wgA = reinterpret_cast<const uint2*>(g_wres_h + (size_t)rowA * RR);
    const uint2* wgB = reinterpret_cast<const uint2*>(g_wres_h + (size_t)rowB * RR);

    for (int t = 1; t < T_; ++t) {
        float uA = 0.f, uB = 0.f;
        if (active && lane == 0) {
            uA = ldcg(&g_u[(size_t)t * RR + rowA]);
            if (haveB) uB = ldcg(&g_u[(size_t)t * RR + rowB]);
        }
        {
            const float4* sp4 = reinterpret_cast<const float4*>(
                g_states + (size_t)(t - 1) * RR);
            fs4[tid] = ldcg4f(sp4 + tid);
        }
        __syncthreads();

        if (active) {
            float accA = 0.f, accB = 0.f;
            #pragma unroll 8
            for (int idx = lane; idx < RR / 4; idx += 32) {
                float4 s = fs4[idx];
                fma4(ldcg2u(wgA + idx), s, accA);
                if (haveB) fma4(ldcg2u(wgB + idx), s, accB);
            }
            #pragma unroll
            for (int o = 16; o; o >>= 1) {
                accA += __shfl_xor_sync(0xffffffffu, accA, o);
                accB += __shfl_xor_sync(0xffffffffu, accB, o);
            }
            if (lane == 0) {
                float* scur = g_states + (size_t)t * RR;
                float xiA = tanhf(uA + accA);
                scur[rowA] = (1.0f - LEAK_) * fs[rowA] + LEAK_ * xiA;
                if (haveB) {
                    float xiB = tanhf(uB + accB);
                    scur[rowB] = (1.0f - LEAK_) * fs[rowB] + LEAK_ * xiB;
                }
            }
        }
        grid_barrier_step(nctas, bstep++);
    }
}

// ---------------------------------------------------------------------------
// GEMM 2: yout = concat(x, states) @ Wout^T + b
// ---------------------------------------------------------------------------
__global__ __launch_bounds__(256) void gemm_out_kernel(
    const float* __restrict__ x, const float* __restrict__ Wout,
    const float* __restrict__ bias, float* __restrict__ C)
{
    const int K = NINT;
    __shared__ float As[8][128];
    __shared__ float Bs[8][128];

    const int bm = blockIdx.y * 128;
    const int bn = blockIdx.x * 128;
    const int tid = threadIdx.x;
    const int tm = (tid >> 4) * 8;
    const int tn = (tid & 15) * 8;
    const int lr = tid >> 1;
    const int lc = (tid & 1) * 4;

    float acc[8][8];
    #pragma unroll
    for (int i = 0; i < 8; i++)
        #pragma unroll
        for (int j = 0; j < 8; j++) acc[i][j] = 0.f;

    for (int kb = 0; kb < K; kb += 8) {
        const int row = bm + lr;
        const int kk  = kb + lc;
        float4 a;
        if (kk < DIN)
            a = *reinterpret_cast<const float4*>(&x[(size_t)row * DIN + kk]);
        else
            a = *reinterpret_cast<const float4*>(&g_states[(size_t)row * RR + (kk - DIN)]);
        float4 b = *reinterpret_cast<const float4*>(&Wout[(size_t)(bn + lr) * K + kk]);
        __syncthreads();
        As[lc + 0][lr] = a.x; As[lc + 1][lr] = a.y; As[lc + 2][lr] = a.z; As[lc + 3][lr] = a.w;
        Bs[lc + 0][lr] = b.x; Bs[lc + 1][lr] = b.y; Bs[lc + 2][lr] = b.z; Bs[lc + 3][lr] = b.w;
        __syncthreads();
        #pragma unroll
        for (int k = 0; k < 8; k++) {
            float4 a0 = *reinterpret_cast<const float4*>(&As[k][tm]);
            float4 a1 = *reinterpret_cast<const float4*>(&As[k][tm + 4]);
            float4 b0 = *reinterpret_cast<const float4*>(&Bs[k][tn]);
            float4 b1 = *reinterpret_cast<const float4*>(&Bs[k][tn + 4]);
            float ar[8] = {a0.x, a0.y, a0.z, a0.w, a1.x, a1.y, a1.z, a1.w};
            float br[8] = {b0.x, b0.y, b0.z, b0.w, b1.x, b1.y, b1.z, b1.w};
            #pragma unroll
            for (int i = 0; i < 8; i++)
                #pragma unroll
                for (int j = 0; j < 8; j++)
                    acc[i][j] = fmaf(ar[i], br[j], acc[i][j]);
        }
    }

    #pragma unroll
    for (int i = 0; i < 8; i++)
        #pragma unroll
        for (int j = 0; j < 8; j++)
            C[(size_t)(bm + tm + i) * DOUT + (bn + tn + j)] = acc[i][j] + bias[bn + tn + j];
}

// ---------------------------------------------------------------------------
extern "C" void kernel_launch(void* const* d_in, const int* in_sizes, int n_in,
                              void* d_out, int out_size)
{
    const float* x      = (const float*)d_in[0];
    const float* Win_w  = (const float*)d_in[1];
    const float* Win_b  = (const float*)d_in[2];
    const float* Wres_w = (const float*)d_in[3];
    const float* Wout_w = (const float*)d_in[4];
    const float* Wout_b = (const float*)d_in[5];
    float* yout = (float*)d_out;

    int dev = 0;
    cudaGetDevice(&dev);
    int sms = 148;
    cudaDeviceGetAttribute(&sms, cudaDevAttrMultiProcessorCount, dev);
    if (sms < 64) sms = 64;
    if (sms > 256) sms = 256;

    cudaError_t attr_err = cudaFuncSetAttribute(
        recur_smem_kernel, cudaFuncAttributeMaxDynamicSharedMemorySize, (int)SMEM_BYTES);
    int nblk = 0;
    cudaError_t occ_err = cudaOccupancyMaxActiveBlocksPerMultiprocessor(
        &nblk, recur_smem_kernel, TPB, SMEM_BYTES);
    const int max_rows = (RR + sms - 1) / sms;
    const bool use_smem = (attr_err == cudaSuccess) &&
                          (occ_err == cudaSuccess) && (nblk >= 1) &&
                          (max_rows <= ROWS_MAX);

    reset_barrier_kernel<<<1, 32>>>();
    convert_wres_kernel<<<1024, 256>>>(Wres_w);

    dim3 g1(RR / 128, T_ / 128);
    gemm_u_kernel<<<g1, 256>>>(x, Win_w, Win_b);

    if (use_smem)
        recur_smem_kernel<<<sms, TPB, SMEM_BYTES>>>(sms);
    else
        recur_fallback<<<sms, 1024>>>(sms);

    dim3 g2(DOUT / 128, T_ / 128);
    gemm_out_kernel<<<g2, 256>>>(x, Wout_w, Wout_b, yout);

    (void)in_sizes; (void)n_in; (void)out_size;
}